// round 4
// baseline (speedup 1.0000x reference)
#include <cuda_runtime.h>

// Ende_3332894622093: B=65536, D=40, HB=20.
// out = [t1 | s2] (B,1,40);  J_T (B,40,40) =
//   [[diag(e4)+JJ12@J21, JJ12*e2], [J21, diag(e2)]]
// d_out: out flattened (n*40) then J_T flattened (n*1600).
//
// Mapping: thread -> (item = tid/20, j = tid%20), 20 threads/item, zero idle
// lanes. Persistent loop: each block handles IPB*NITER items so per-thread
// weight registers (rows+cols for fixed j) amortize across NITER items.

#define IPB   16            // items per iteration
#define TPB   (IPB * 20)    // 320 threads
#define NITER 7
#define GRID  592           // 592*16*7 = 66304 >= 65536
#define WSS   528           // per-item smem stride (floats), 16 mod 32 banks
// per-item smem: xs[0..40) bb[40..80)(float2 x20) s2s[80..100) jjs[100..500)

__global__ __launch_bounds__(TPB)
void ende_kernel(const float* __restrict__ src,
                 const float* __restrict__ w1,
                 const float* __restrict__ w2,
                 const float* __restrict__ w3,
                 const float* __restrict__ w4,
                 float* __restrict__ outp,
                 float* __restrict__ jt,
                 int n)
{
    __shared__ __align__(16) float ws[IPB * WSS];

    const int tid   = threadIdx.x;
    const int itemL = tid / 20;
    const int j     = tid % 20;
    float* S = &ws[itemL * WSS];

    // ---- weights into registers (once, amortized over NITER items) ----
    float w1r[20], w2r[20], w3r[20], w4r[20], w1c[20], w2c[20];
    {
        const float4* g1 = (const float4*)(w1 + j * 20);
        const float4* g2 = (const float4*)(w2 + j * 20);
        const float4* g3 = (const float4*)(w3 + j * 20);
        const float4* g4 = (const float4*)(w4 + j * 20);
        #pragma unroll
        for (int k4 = 0; k4 < 5; k4++) {
            *(float4*)&w1r[4 * k4] = g1[k4];
            *(float4*)&w2r[4 * k4] = g2[k4];
            *(float4*)&w3r[4 * k4] = g3[k4];
            *(float4*)&w4r[4 * k4] = g4[k4];
        }
        #pragma unroll
        for (int k = 0; k < 20; k++) {
            w1c[k] = w1[k * 20 + j];
            w2c[k] = w2[k * 20 + j];
        }
    }

    const int base = blockIdx.x * (IPB * NITER);
    const bool odd = (j & 1);

    for (int iter = 0; iter < NITER; iter++) {
        __syncthreads();   // previous iteration's smem readers done

        // ---- cooperative x load ----
        if (tid < IPB * 10) {
            int it = tid / 10, c = tid % 10;
            int gb = base + iter * IPB + it;
            if (gb < n) {
                float4 v = ((const float4*)(src + (size_t)gb * 40))[c];
                *(float4*)&ws[it * WSS + c * 4] = v;
            }
        }
        __syncthreads();

        const int b   = base + iter * IPB + itemL;
        const bool act = (b < n);

        // ---- phase B: f1, f2, e2, (b1,b2), s2 ----
        float e2j, s2j;
        {
            float acc1 = 0.f, acc2 = 0.f;
            const float4* xv = (const float4*)S;
            #pragma unroll
            for (int k4 = 0; k4 < 5; k4++) {
                float4 xx = xv[k4];
                acc1 += xx.x * w1r[4*k4] + xx.y * w1r[4*k4+1] + xx.z * w1r[4*k4+2] + xx.w * w1r[4*k4+3];
                acc2 += xx.x * w2r[4*k4] + xx.y * w2r[4*k4+1] + xx.z * w2r[4*k4+2] + xx.w * w2r[4*k4+3];
            }
            float f1 = tanhf(acc1);
            float f2 = tanhf(acc2);
            e2j = expf(f2);
            float p2  = S[20 + j];
            float p2e = p2 * e2j;
            s2j = p2e + f1;
            ((float2*)&S[40])[j] = make_float2(1.f - f1 * f1, p2e * (1.f - f2 * f2));
            S[80 + j] = s2j;
        }
        __syncthreads();

        // ---- phase C: f3, f4, e4, t1, JJ12 row j ----
        float e4j;
        {
            float acc3 = 0.f, acc4 = 0.f;
            const float4* sv = (const float4*)&S[80];
            #pragma unroll
            for (int k4 = 0; k4 < 5; k4++) {
                float4 xx = sv[k4];
                acc3 += xx.x * w3r[4*k4] + xx.y * w3r[4*k4+1] + xx.z * w3r[4*k4+2] + xx.w * w3r[4*k4+3];
                acc4 += xx.x * w4r[4*k4] + xx.y * w4r[4*k4+1] + xx.z * w4r[4*k4+2] + xx.w * w4r[4*k4+3];
            }
            float f3 = tanhf(acc3);
            float f4 = tanhf(acc4);
            e4j = expf(f4);
            float s1  = S[j];
            float s1e = s1 * e4j;
            float a3 = 1.f - f3 * f3;
            float a4 = s1e * (1.f - f4 * f4);
            float4* jj = (float4*)&S[100 + j * 20];
            #pragma unroll
            for (int k4 = 0; k4 < 5; k4++) {
                float4 r;
                r.x = a3 * w3r[4*k4]   + a4 * w4r[4*k4];
                r.y = a3 * w3r[4*k4+1] + a4 * w4r[4*k4+1];
                r.z = a3 * w3r[4*k4+2] + a4 * w4r[4*k4+2];
                r.w = a3 * w3r[4*k4+3] + a4 * w4r[4*k4+3];
                jj[k4] = r;
            }
            if (act) {
                outp[(size_t)b * 40 + j]      = s1e + f3;  // t1
                outp[(size_t)b * 40 + 20 + j] = s2j;
            }
        }
        __syncthreads();

        float* J = jt + (size_t)b * 1600;

        // ---- phase D: my_col = J21 col j; full BL|BR rows via 1 shfl + STG.64 ----
        float my_col[20];
        #pragma unroll
        for (int kk = 0; kk < 10; kk++) {
            float4 bbp = *(const float4*)&S[40 + 4 * kk];  // (b1,b2) for k=2kk,2kk+1
            #pragma unroll
            for (int s = 0; s < 2; s++) {
                int k = 2 * kk + s;
                float b1v = s ? bbp.z : bbp.x;
                float b2v = s ? bbp.w : bbp.y;
                float c = b1v * w1c[k] + b2v * w2c[k];
                my_col[k] = c;
                float brv = (k == j) ? e2j : 0.f;
                // even lane needs partner's c; odd lane needs partner's brv
                float recv = __shfl_xor_sync(0xFFFFFFFFu, odd ? c : brv, 1);
                if (act) {
                    if (odd)
                        __stcs((float2*)&J[(20 + k) * 40 + 20 + (j - 1)], make_float2(recv, brv));
                    else
                        __stcs((float2*)&J[(20 + k) * 40 + j], make_float2(c, recv));
                }
            }
        }

        // ---- phase E: TL = diag(e4)+JJ12@J21, TR = JJ12*e2; 1 shfl + STG.64 ----
        #pragma unroll 4
        for (int i = 0; i < 20; i++) {
            const float4* jjr = (const float4*)&S[100 + i * 20];
            float acc = 0.f;
            #pragma unroll
            for (int k4 = 0; k4 < 5; k4++) {
                float4 v = jjr[k4];
                acc += v.x * my_col[4 * k4 + 0] + v.y * my_col[4 * k4 + 1]
                     + v.z * my_col[4 * k4 + 2] + v.w * my_col[4 * k4 + 3];
            }
            if (i == j) acc += e4j;
            float trv = S[100 + i * 20 + j] * e2j;
            // even lane needs partner's acc; odd lane needs partner's trv
            float recv = __shfl_xor_sync(0xFFFFFFFFu, odd ? acc : trv, 1);
            if (act) {
                if (odd)
                    __stcs((float2*)&J[i * 40 + 20 + (j - 1)], make_float2(recv, trv));
                else
                    __stcs((float2*)&J[i * 40 + j], make_float2(acc, recv));
            }
        }
    }
}

extern "C" void kernel_launch(void* const* d_in, const int* in_sizes, int n_in,
                              void* d_out, int out_size)
{
    const float* src = (const float*)d_in[0];
    const float* w1  = (const float*)d_in[1];
    const float* w2  = (const float*)d_in[2];
    const float* w3  = (const float*)d_in[3];
    const float* w4  = (const float*)d_in[4];

    int n = in_sizes[0] / 40;
    float* outp = (float*)d_out;
    float* jt   = (float*)d_out + (size_t)n * 40;

    ende_kernel<<<GRID, TPB>>>(src, w1, w2, w3, w4, outp, jt, n);
}

// round 5
// speedup vs baseline: 1.3313x; 1.3313x over previous
#include <cuda_runtime.h>

// Ende_3332894622093: B=65536, D=40, HB=20.
// out = [t1 | s2] (B,1,40);  J_T (B,40,40) =
//   [[diag(e4)+JJ12@J21, JJ12*e2], [J21, diag(e2)]]
// d_out: out flattened (n*40) then J_T flattened (n*1600).
//
// Mapping: thread -> (item = tid/20, j = tid%20). Phase D/E use paired
// columns: lanes (je, je+1) both hold J21[:, je..je+1] (float2); the even
// lane produces rows 0..9 of TL/TR, the odd lane rows 10..19. One LDS.128
// then serves two jjs rows x two items per instruction, and no shfl needed.

#define IPB 16            // items per block (65536 % 16 == 0)
#define TPB (IPB * 20)    // 320 threads
#define WSS 560           // per-item smem stride (floats); 560 mod 32 = 16 banks
// per-item: xs[0..40) bb[40..80) s2s[80..100) jjs[100..500) e2s[500..520) e4s[520..540)

__global__ __launch_bounds__(TPB, 2)
void ende_kernel(const float* __restrict__ src,
                 const float* __restrict__ w1,
                 const float* __restrict__ w2,
                 const float* __restrict__ w3,
                 const float* __restrict__ w4,
                 float* __restrict__ outp,
                 float* __restrict__ jt,
                 int n)
{
    __shared__ float w1s[400], w2s[400], w3s[400], w4s[400];
    __shared__ __align__(16) float ws[IPB * WSS];

    const int tid = threadIdx.x;
    for (int i = tid; i < 400; i += TPB) {
        w1s[i] = w1[i];
        w2s[i] = w2[i];
        w3s[i] = w3[i];
        w4s[i] = w4[i];
    }

    const int itemL = tid / 20;
    const int j     = tid % 20;
    const int b     = blockIdx.x * IPB + itemL;
    const bool act  = (b < n);
    float* S = &ws[itemL * WSS];

    // ---- cooperative x load ----
    if (tid < IPB * 10) {
        int it = tid / 10, c = tid % 10;
        if (blockIdx.x * IPB + it < n) {
            float4 v = ((const float4*)(src + (size_t)(blockIdx.x * IPB + it) * 40))[c];
            *(float4*)&ws[it * WSS + c * 4] = v;
        }
    }
    __syncthreads();

    // ---- phase B: f1, f2, e2, (b1,b2), s2 ----
    float s2j;
    {
        float acc1 = 0.f, acc2 = 0.f;
        const float4* xv  = (const float4*)S;
        const float4* w1r = (const float4*)&w1s[j * 20];
        const float4* w2r = (const float4*)&w2s[j * 20];
        #pragma unroll
        for (int k4 = 0; k4 < 5; k4++) {
            float4 xx = xv[k4], a = w1r[k4], c = w2r[k4];
            acc1 += xx.x * a.x + xx.y * a.y + xx.z * a.z + xx.w * a.w;
            acc2 += xx.x * c.x + xx.y * c.y + xx.z * c.z + xx.w * c.w;
        }
        float f1 = tanhf(acc1);
        float f2 = tanhf(acc2);
        float e2 = expf(f2);
        float p2  = S[20 + j];
        float p2e = p2 * e2;
        s2j = p2e + f1;
        ((float2*)&S[40])[j] = make_float2(1.f - f1 * f1, p2e * (1.f - f2 * f2));
        S[80 + j]  = s2j;
        S[500 + j] = e2;
    }
    __syncthreads();

    // ---- phase C: f3, f4, e4, t1, JJ12 row j ----
    {
        float acc3 = 0.f, acc4 = 0.f;
        const float4* sv  = (const float4*)&S[80];
        const float4* w3r = (const float4*)&w3s[j * 20];
        const float4* w4r = (const float4*)&w4s[j * 20];
        #pragma unroll
        for (int k4 = 0; k4 < 5; k4++) {
            float4 xx = sv[k4], a = w3r[k4], c = w4r[k4];
            acc3 += xx.x * a.x + xx.y * a.y + xx.z * a.z + xx.w * a.w;
            acc4 += xx.x * c.x + xx.y * c.y + xx.z * c.z + xx.w * c.w;
        }
        float f3 = tanhf(acc3);
        float f4 = tanhf(acc4);
        float e4 = expf(f4);
        float s1  = S[j];
        float s1e = s1 * e4;
        float a3 = 1.f - f3 * f3;
        float a4 = s1e * (1.f - f4 * f4);
        float4* jj = (float4*)&S[100 + j * 20];
        #pragma unroll
        for (int k4 = 0; k4 < 5; k4++) {
            float4 a_ = *(const float4*)&w3s[j * 20 + 4 * k4];
            float4 c_ = *(const float4*)&w4s[j * 20 + 4 * k4];
            float4 r;
            r.x = a3 * a_.x + a4 * c_.x;
            r.y = a3 * a_.y + a4 * c_.y;
            r.z = a3 * a_.z + a4 * c_.z;
            r.w = a3 * a_.w + a4 * c_.w;
            jj[k4] = r;
        }
        S[520 + j] = e4;
        if (act) {
            outp[(size_t)b * 40 + j]      = s1e + f3;  // t1
            outp[(size_t)b * 40 + 20 + j] = s2j;
        }
    }
    __syncthreads();

    float* J = jt + (size_t)b * 1600;
    const int p  = j & 1;
    const int je = j & ~1;

    // ---- phase D: my_col2 = J21[:, je..je+1] (both lanes of pair, dup) ----
    float2 mc[20];
    #pragma unroll
    for (int kk = 0; kk < 10; kk++) {
        float4 bbp = *(const float4*)&S[40 + 4 * kk];  // (b1,b2) for k=2kk,2kk+1
        #pragma unroll
        for (int s = 0; s < 2; s++) {
            int k = 2 * kk + s;
            float b1v = s ? bbp.z : bbp.x;
            float b2v = s ? bbp.w : bbp.y;
            float2 wa = *(const float2*)&w1s[k * 20 + je];
            float2 wb = *(const float2*)&w2s[k * 20 + je];
            mc[k].x = b1v * wa.x + b2v * wb.x;
            mc[k].y = b1v * wa.y + b2v * wb.y;
        }
    }

    const float2 e2p = *(const float2*)&S[500 + je];
    const float2 e4p = *(const float2*)&S[520 + je];

    // ---- BL/BR stores: even lane rows k=0..9, odd lane k=10..19 ----
    if (act) {
        if (p == 0) {
            #pragma unroll
            for (int kk = 0; kk < 10; kk++) {
                __stcs((float2*)&J[(20 + kk) * 40 + je], mc[kk]);
                float2 br = make_float2(kk == je ? e2p.x : 0.f,
                                        kk == je + 1 ? e2p.y : 0.f);
                __stcs((float2*)&J[(20 + kk) * 40 + 20 + je], br);
            }
        } else {
            #pragma unroll
            for (int kk = 0; kk < 10; kk++) {
                int k = 10 + kk;
                __stcs((float2*)&J[(20 + k) * 40 + je], mc[10 + kk]);
                float2 br = make_float2(k == je ? e2p.x : 0.f,
                                        k == je + 1 ? e2p.y : 0.f);
                __stcs((float2*)&J[(20 + k) * 40 + 20 + je], br);
            }
        }
    }

    // ---- phase E: even lane rows i=0..9, odd rows 10..19; cols je,je+1 ----
    const int ibase = p ? 10 : 0;
    #pragma unroll
    for (int ii = 0; ii < 10; ii++) {
        int i = ibase + ii;
        const float4* jjr = (const float4*)&S[100 + i * 20];
        float jrow[20];
        #pragma unroll
        for (int k4 = 0; k4 < 5; k4++) {
            float4 v = jjr[k4];
            jrow[4 * k4 + 0] = v.x;
            jrow[4 * k4 + 1] = v.y;
            jrow[4 * k4 + 2] = v.z;
            jrow[4 * k4 + 3] = v.w;
        }
        float2 acc = make_float2(0.f, 0.f);
        #pragma unroll
        for (int k = 0; k < 20; k++) {
            acc.x += jrow[k] * mc[k].x;
            acc.y += jrow[k] * mc[k].y;
        }
        if (i == je)     acc.x += e4p.x;
        if (i == je + 1) acc.y += e4p.y;
        float2 jp = *(const float2*)&S[100 + i * 20 + je];
        float2 tr = make_float2(jp.x * e2p.x, jp.y * e2p.y);
        if (act) {
            __stcs((float2*)&J[i * 40 + je], acc);
            __stcs((float2*)&J[i * 40 + 20 + je], tr);
        }
    }
}

extern "C" void kernel_launch(void* const* d_in, const int* in_sizes, int n_in,
                              void* d_out, int out_size)
{
    const float* src = (const float*)d_in[0];
    const float* w1  = (const float*)d_in[1];
    const float* w2  = (const float*)d_in[2];
    const float* w3  = (const float*)d_in[3];
    const float* w4  = (const float*)d_in[4];

    int n = in_sizes[0] / 40;
    float* outp = (float*)d_out;
    float* jt   = (float*)d_out + (size_t)n * 40;

    int blocks = (n + IPB - 1) / IPB;
    ende_kernel<<<blocks, TPB>>>(src, w1, w2, w3, w4, outp, jt, n);
}